// round 8
// baseline (speedup 1.0000x reference)
#include <cuda_runtime.h>

#define MAXN   100000
#define MAXE   3200000
#define IN_DIM 128
#define HID    64
#define G_NUM  256
#define SCAN_B 1024

typedef unsigned long long u64;

// packed fp32x2 helpers (sm_100+): 2 fp32 FMA per issue slot
__device__ __forceinline__ u64 pack2(float lo, float hi) {
    u64 r; asm("mov.b64 %0, {%1, %2};" : "=l"(r) : "f"(lo), "f"(hi)); return r;
}
__device__ __forceinline__ u64 ffma2(u64 a, u64 b, u64 c) {
    u64 d; asm("fma.rn.f32x2 %0, %1, %2, %3;" : "=l"(d) : "l"(a), "l"(b), "l"(c)); return d;
}
__device__ __forceinline__ float2 unpack2(u64 v) {
    float2 f; asm("mov.b64 {%0, %1}, %2;" : "=f"(f.x), "=f"(f.y) : "l"(v)); return f;
}

// ---------------- device scratch (no allocation allowed) ----------------
__device__ __align__(16) float g_h   [MAXN * (size_t)HID];  // GEMM output (xl)
__device__ __align__(16) float g_acc [MAXN * (size_t)HID];  // gathered layer output
__device__ __align__(16) float2 g_edge[MAXE];               // {row bits, dis[row]*ew}
__device__ float g_deg [MAXN];
__device__ float g_dis [MAXN];
__device__ int   g_cntn[MAXN];
__device__ int   g_off [MAXN + 1];       // CSR offsets + sentinel E
__device__ int   g_cur [MAXN];
__device__ int   g_bsum[(MAXN + SCAN_B - 1) / SCAN_B];
__device__ int   g_boff[(MAXN + SCAN_B - 1) / SCAN_B];
__device__ int   g_gs  [G_NUM + 1];
__device__ int   g_gcnt[G_NUM];
__device__ __align__(16) float g_sums[G_NUM * HID];

// ---------------- kernels ----------------

__global__ void k_reset(int n) {
    int i = blockIdx.x * blockDim.x + threadIdx.x;
    if (i < n) { g_deg[i] = 1.0f; g_cntn[i] = 0; }   // self-loop weight 1
}

__global__ void k_deg(const int* __restrict__ col,
                      const float* __restrict__ ew, int E) {
    int e = blockIdx.x * blockDim.x + threadIdx.x;
    if (e < E) {
        int c = col[e];
        atomicAdd(&g_deg[c], ew[e]);
        atomicAdd(&g_cntn[c], 1);
    }
}

// block-local exclusive scan over g_cntn (+ fused dis = rsqrt(deg))
__global__ void k_scan1(int n) {
    __shared__ int s[2][SCAN_B];
    const int t = threadIdx.x;
    const int i = blockIdx.x * SCAN_B + t;
    if (i < n) g_dis[i] = rsqrtf(g_deg[i]);
    int v = (i < n) ? g_cntn[i] : 0;
    s[0][t] = v;
    __syncthreads();
    int src = 0;
    #pragma unroll
    for (int d = 1; d < SCAN_B; d <<= 1) {
        int x = s[src][t];
        if (t >= d) x += s[src][t - d];
        s[1 - src][t] = x;
        src = 1 - src;
        __syncthreads();
    }
    int incl = s[src][t];
    if (i < n) g_off[i] = incl - v;
    if (t == SCAN_B - 1) g_bsum[blockIdx.x] = incl;
}

__global__ void k_scan2(int nb) {
    __shared__ int s[128];
    const int t = threadIdx.x;
    int v = (t < nb) ? g_bsum[t] : 0;
    s[t] = v;
    __syncthreads();
    #pragma unroll
    for (int d = 1; d < 128; d <<= 1) {
        int x = s[t];
        if (t >= d) x += s[t - d];
        __syncthreads();
        s[t] = x;
        __syncthreads();
    }
    if (t < nb) g_boff[t] = s[t] - v;
}

__global__ void k_scan3(const int* __restrict__ batch, int n, int E) {
    int i = blockIdx.x * blockDim.x + threadIdx.x;
    if (i >= n) return;
    int o = g_off[i] + g_boff[i >> 10];
    g_off[i] = o;
    g_cur[i] = o;
    if (i == 0) g_off[n] = E;
    int b = batch[i];
    int p = (i == 0) ? -1 : batch[i - 1];
    for (int g = p + 1; g <= b; ++g) g_gs[g] = i;
    if (i == n - 1)
        for (int g = b + 1; g <= G_NUM; ++g) g_gs[g] = n;
}

__global__ void k_place(const int* __restrict__ row,
                        const int* __restrict__ col,
                        const float* __restrict__ ew, int E) {
    int e = blockIdx.x * blockDim.x + threadIdx.x;
    if (e >= E) return;
    int r = row[e];
    int c = col[e];
    float nm = g_dis[r] * ew[e];
    int pos = atomicAdd(&g_cur[c], 1);
    g_edge[pos] = make_float2(__int_as_float(r), nm);
}

// GEMM: g_h[n][HID] = X[n][K] @ W[K][HID]; SRC_ACC reads relu(g_acc).
// 256 thr/CTA; thread = (hq in 0..7 cols-group, rg in 0..31 rows-group);
// each thread: 4 rows x 8 cols, x straight from global (read-once), W in smem.
template<int K, bool SRC_ACC>
__global__ void k_gemm(const float* __restrict__ X,
                       const float* __restrict__ W, int n) {
    __shared__ float sw[K * HID];
    const int t = threadIdx.x;

    #pragma unroll
    for (int i = t; i < K * HID / 4; i += 256)
        ((float4*)sw)[i] = ((const float4*)W)[i];
    __syncthreads();

    const int hq4 = (t & 7) * 8;        // starting column (8 cols per thread)
    const int rg  = t >> 3;             // 0..31
    const int r0  = blockIdx.x * 128 + rg * 4;

    const float* xbase = SRC_ACC ? g_acc : X;
    const int ra = min(r0 + 0, n - 1);
    const int rb = min(r0 + 1, n - 1);
    const int rc = min(r0 + 2, n - 1);
    const int rd = min(r0 + 3, n - 1);
    const float4* xA = (const float4*)(xbase + (size_t)ra * K);
    const float4* xB = (const float4*)(xbase + (size_t)rb * K);
    const float4* xC = (const float4*)(xbase + (size_t)rc * K);
    const float4* xD = (const float4*)(xbase + (size_t)rd * K);

    u64 acc[4][4];
    #pragma unroll
    for (int i = 0; i < 4; i++)
        #pragma unroll
        for (int j = 0; j < 4; j++) acc[i][j] = 0;

    #pragma unroll 2
    for (int q = 0; q < K / 4; q++) {
        float4 va = xA[q], vb = xB[q], vc = xC[q], vd = xD[q];
        if (SRC_ACC) {
            va.x=fmaxf(va.x,0.f); va.y=fmaxf(va.y,0.f); va.z=fmaxf(va.z,0.f); va.w=fmaxf(va.w,0.f);
            vb.x=fmaxf(vb.x,0.f); vb.y=fmaxf(vb.y,0.f); vb.z=fmaxf(vb.z,0.f); vb.w=fmaxf(vb.w,0.f);
            vc.x=fmaxf(vc.x,0.f); vc.y=fmaxf(vc.y,0.f); vc.z=fmaxf(vc.z,0.f); vc.w=fmaxf(vc.w,0.f);
            vd.x=fmaxf(vd.x,0.f); vd.y=fmaxf(vd.y,0.f); vd.z=fmaxf(vd.z,0.f); vd.w=fmaxf(vd.w,0.f);
        }
        const float* pa = (const float*)&va;
        const float* pb = (const float*)&vb;
        const float* pc = (const float*)&vc;
        const float* pd = (const float*)&vd;
        #pragma unroll
        for (int kk = 0; kk < 4; kk++) {
            const int k = q * 4 + kk;
            const float4 w0 = *(const float4*)(sw + k * HID + hq4);
            const float4 w1 = *(const float4*)(sw + k * HID + hq4 + 4);
            const u64 wp0 = pack2(w0.x, w0.y);
            const u64 wp1 = pack2(w0.z, w0.w);
            const u64 wp2 = pack2(w1.x, w1.y);
            const u64 wp3 = pack2(w1.z, w1.w);
            u64 xp;
            xp = pack2(pa[kk], pa[kk]);
            acc[0][0]=ffma2(xp,wp0,acc[0][0]); acc[0][1]=ffma2(xp,wp1,acc[0][1]);
            acc[0][2]=ffma2(xp,wp2,acc[0][2]); acc[0][3]=ffma2(xp,wp3,acc[0][3]);
            xp = pack2(pb[kk], pb[kk]);
            acc[1][0]=ffma2(xp,wp0,acc[1][0]); acc[1][1]=ffma2(xp,wp1,acc[1][1]);
            acc[1][2]=ffma2(xp,wp2,acc[1][2]); acc[1][3]=ffma2(xp,wp3,acc[1][3]);
            xp = pack2(pc[kk], pc[kk]);
            acc[2][0]=ffma2(xp,wp0,acc[2][0]); acc[2][1]=ffma2(xp,wp1,acc[2][1]);
            acc[2][2]=ffma2(xp,wp2,acc[2][2]); acc[2][3]=ffma2(xp,wp3,acc[2][3]);
            xp = pack2(pd[kk], pd[kk]);
            acc[3][0]=ffma2(xp,wp0,acc[3][0]); acc[3][1]=ffma2(xp,wp1,acc[3][1]);
            acc[3][2]=ffma2(xp,wp2,acc[3][2]); acc[3][3]=ffma2(xp,wp3,acc[3][3]);
        }
    }

    #pragma unroll
    for (int i = 0; i < 4; i++) {
        const int gr = r0 + i;
        if (gr < n) {
            float2 l0 = unpack2(acc[i][0]), l1 = unpack2(acc[i][1]);
            float2 l2 = unpack2(acc[i][2]), l3 = unpack2(acc[i][3]);
            float* dst = g_h + (size_t)gr * HID + hq4;
            *(float4*)(dst)     = make_float4(l0.x, l0.y, l1.x, l1.y);
            *(float4*)(dst + 4) = make_float4(l2.x, l2.y, l3.x, l3.y);
        }
    }
}

// per-node CSR gather: 16 lanes/node, lane owns one float4 column chunk.
// out = bias + dis^2*h[self] + dis[node] * sum_e (dis[row_e]*ew_e) * h[row_e]
__global__ void k_gather(const float* __restrict__ b, int n) {
    int tid = blockIdx.x * blockDim.x + threadIdx.x;
    int node = tid >> 4;
    if (node >= n) return;
    const int q = tid & 15;

    int e     = g_off[node];
    const int e_end = g_off[node + 1];

    u64 e0 = 0, e1 = 0;

    for (; e + 3 < e_end; e += 4) {
        float2 rA = g_edge[e];
        float2 rB = g_edge[e + 1];
        float2 rC = g_edge[e + 2];
        float2 rD = g_edge[e + 3];
        float4 vA = ((const float4*)(g_h + (size_t)__float_as_int(rA.x) * HID))[q];
        float4 vB = ((const float4*)(g_h + (size_t)__float_as_int(rB.x) * HID))[q];
        float4 vC = ((const float4*)(g_h + (size_t)__float_as_int(rC.x) * HID))[q];
        float4 vD = ((const float4*)(g_h + (size_t)__float_as_int(rD.x) * HID))[q];
        u64 nA = pack2(rA.y, rA.y), nB = pack2(rB.y, rB.y);
        u64 nC = pack2(rC.y, rC.y), nD = pack2(rD.y, rD.y);
        e0 = ffma2(nA, pack2(vA.x, vA.y), e0); e1 = ffma2(nA, pack2(vA.z, vA.w), e1);
        e0 = ffma2(nB, pack2(vB.x, vB.y), e0); e1 = ffma2(nB, pack2(vB.z, vB.w), e1);
        e0 = ffma2(nC, pack2(vC.x, vC.y), e0); e1 = ffma2(nC, pack2(vC.z, vC.w), e1);
        e0 = ffma2(nD, pack2(vD.x, vD.y), e0); e1 = ffma2(nD, pack2(vD.z, vD.w), e1);
    }
    for (; e < e_end; e++) {
        float2 r0 = g_edge[e];
        float4 v0 = ((const float4*)(g_h + (size_t)__float_as_int(r0.x) * HID))[q];
        u64 n0 = pack2(r0.y, r0.y);
        e0 = ffma2(n0, pack2(v0.x, v0.y), e0);
        e1 = ffma2(n0, pack2(v0.z, v0.w), e1);
    }

    const float d  = g_dis[node];
    const float dd = d * d;
    float4 bq = ((const float4*)b)[q];
    float4 h0 = ((const float4*)(g_h + (size_t)node * HID))[q];
    float2 lo = unpack2(e0), hi = unpack2(e1);
    float4 out;
    out.x = bq.x + dd * h0.x + d * lo.x;
    out.y = bq.y + dd * h0.y + d * lo.y;
    out.z = bq.z + dd * h0.z + d * hi.x;
    out.w = bq.w + dd * h0.w + d * hi.y;
    ((float4*)(g_acc + (size_t)node * HID))[q] = out;
}

__global__ void k_pool(int n) {
    const int g = blockIdx.x;
    const int t = threadIdx.x;
    const int q = t & 15;
    const int sub = t >> 4;
    const int s = g_gs[g], e = g_gs[g + 1];

    float4 acc = make_float4(0.f, 0.f, 0.f, 0.f);
    for (int i = s + sub; i < e; i += 16) {
        float4 v = ((const float4*)(g_acc + (size_t)i * HID))[q];
        acc.x += fmaxf(v.x, 0.f); acc.y += fmaxf(v.y, 0.f);
        acc.z += fmaxf(v.z, 0.f); acc.w += fmaxf(v.w, 0.f);
    }
    __shared__ float4 sm[256];
    sm[t] = acc;
    __syncthreads();
    if (sub == 0) {
        float4 a = acc;
        #pragma unroll
        for (int k = 1; k < 16; k++) {
            float4 bb = sm[k * 16 + q];
            a.x += bb.x; a.y += bb.y; a.z += bb.z; a.w += bb.w;
        }
        ((float4*)(g_sums + g * HID))[q] = a;
        if (q == 0) g_gcnt[g] = e - s;
    }
}

__global__ void k_final(const float* __restrict__ Wc,
                        const float* __restrict__ bc,
                        float* __restrict__ out) {
    int g = blockIdx.x * blockDim.x + threadIdx.x;
    if (g >= G_NUM) return;
    const float c = fmaxf((float)g_gcnt[g], 1.0f);
    float acc = 0.0f;
    #pragma unroll
    for (int h = 0; h < HID; h++)
        acc += g_sums[g * HID + h] * Wc[h];
    out[g] = acc / c + bc[0];
}

// ---------------- launcher ----------------
extern "C" void kernel_launch(void* const* d_in, const int* in_sizes, int n_in,
                              void* d_out, int out_size) {
    const float* x     = (const float*)d_in[0];
    const int*   ei    = (const int*)  d_in[1];   // int32 (JAX x64 disabled)
    const float* ew    = (const float*)d_in[2];
    const int*   batch = (const int*)  d_in[3];   // int32
    const float* W1    = (const float*)d_in[4];
    const float* b1    = (const float*)d_in[5];
    const float* W2    = (const float*)d_in[6];
    const float* b2    = (const float*)d_in[7];
    const float* Wc    = (const float*)d_in[8];
    const float* bc    = (const float*)d_in[9];
    float* out = (float*)d_out;

    const int n = in_sizes[0] / IN_DIM;   // 100000
    const int E = in_sizes[2];            // 3200000
    const int* row = ei;
    const int* col = ei + E;
    const int T = 256;
    const int nb = (n + SCAN_B - 1) / SCAN_B;

    k_reset<<<(n + T - 1) / T, T>>>(n);
    k_deg  <<<(E + T - 1) / T, T>>>(col, ew, E);
    k_scan1<<<nb, SCAN_B>>>(n);
    k_gemm<IN_DIM, false><<<(n + 127) / 128, T>>>(x, W1, n);  // independent of scan chain
    k_scan2<<<1, 128>>>(nb);
    k_scan3<<<(n + T - 1) / T, T>>>(batch, n, E);
    k_place<<<(E + T - 1) / T, T>>>(row, col, ew, E);

    k_gather<<<(n * 16 + T - 1) / T, T>>>(b1, n);             // layer 1

    k_gemm<HID, true><<<(n + 127) / 128, T>>>(nullptr, W2, n);// layer 2
    k_gather<<<(n * 16 + T - 1) / T, T>>>(b2, n);

    k_pool <<<G_NUM, 256>>>(n);
    k_final<<<1, T>>>(Wc, bc, out);
}

// round 9
// speedup vs baseline: 1.1454x; 1.1454x over previous
#include <cuda_runtime.h>

#define MAXN   100000
#define MAXE   3200000
#define IN_DIM 128
#define HID    64
#define G_NUM  256
#define SCAN_B 1024

typedef unsigned long long u64;
typedef unsigned int u32;

// ---- packed fp32x2 helpers (sm_100+) ----
__device__ __forceinline__ u64 pack2(float lo, float hi) {
    u64 r; asm("mov.b64 %0, {%1, %2};" : "=l"(r) : "f"(lo), "f"(hi)); return r;
}
__device__ __forceinline__ u64 ffma2(u64 a, u64 b, u64 c) {
    u64 d; asm("fma.rn.f32x2 %0, %1, %2, %3;" : "=l"(d) : "l"(a), "l"(b), "l"(c)); return d;
}
__device__ __forceinline__ float2 unpack2(u64 v) {
    float2 f; asm("mov.b64 {%0, %1}, %2;" : "=f"(f.x), "=f"(f.y) : "l"(v)); return f;
}
// round-to-nearest bf16x2 from two f32 (lo in low 16 bits)
__device__ __forceinline__ u32 cvt_bf16x2(float lo, float hi) {
    u32 r; asm("cvt.rn.bf16x2.f32 %0, %1, %2;" : "=r"(r) : "f"(hi), "f"(lo)); return r;
}
// expand bf16x2 -> packed f32x2 (exact, 2 LOPs + pack)
__device__ __forceinline__ u64 bf2f2(u32 u) {
    u32 lo = u << 16;
    u32 hi = u & 0xFFFF0000u;
    u64 r; asm("mov.b64 %0, {%1, %2};" : "=l"(r) : "r"(lo), "r"(hi)); return r;
}

// ---------------- device scratch (no allocation allowed) ----------------
__device__ __align__(16) u32   g_hb [MAXN * (size_t)(HID / 2)]; // bf16x2 GEMM output
__device__ __align__(16) float g_acc[MAXN * (size_t)HID];       // gathered layer output (f32)
__device__ __align__(16) float2 g_edge[MAXE];                   // {row bits, dis[row]*ew}
__device__ float g_deg [MAXN];
__device__ float g_dis [MAXN];
__device__ int   g_cntn[MAXN];
__device__ int   g_off [MAXN + 1];
__device__ int   g_cur [MAXN];
__device__ int   g_bsum[(MAXN + SCAN_B - 1) / SCAN_B];
__device__ int   g_boff[(MAXN + SCAN_B - 1) / SCAN_B];
__device__ int   g_gs  [G_NUM + 1];
__device__ int   g_gcnt[G_NUM];
__device__ __align__(16) float g_sums[G_NUM * HID];

// ---------------- prolog kernels ----------------

__global__ void k_reset(int n) {
    int i = blockIdx.x * blockDim.x + threadIdx.x;
    if (i < n) { g_deg[i] = 1.0f; g_cntn[i] = 0; }
}

__global__ void k_deg(const int* __restrict__ col,
                      const float* __restrict__ ew, int E) {
    int e = blockIdx.x * blockDim.x + threadIdx.x;
    if (e < E) {
        int c = col[e];
        atomicAdd(&g_deg[c], ew[e]);
        atomicAdd(&g_cntn[c], 1);
    }
}

__global__ void k_scan1(int n) {
    __shared__ int s[2][SCAN_B];
    const int t = threadIdx.x;
    const int i = blockIdx.x * SCAN_B + t;
    if (i < n) g_dis[i] = rsqrtf(g_deg[i]);
    int v = (i < n) ? g_cntn[i] : 0;
    s[0][t] = v;
    __syncthreads();
    int src = 0;
    #pragma unroll
    for (int d = 1; d < SCAN_B; d <<= 1) {
        int x = s[src][t];
        if (t >= d) x += s[src][t - d];
        s[1 - src][t] = x;
        src = 1 - src;
        __syncthreads();
    }
    int incl = s[src][t];
    if (i < n) g_off[i] = incl - v;
    if (t == SCAN_B - 1) g_bsum[blockIdx.x] = incl;
}

__global__ void k_scan2(int nb) {
    __shared__ int s[128];
    const int t = threadIdx.x;
    int v = (t < nb) ? g_bsum[t] : 0;
    s[t] = v;
    __syncthreads();
    #pragma unroll
    for (int d = 1; d < 128; d <<= 1) {
        int x = s[t];
        if (t >= d) x += s[t - d];
        __syncthreads();
        s[t] = x;
        __syncthreads();
    }
    if (t < nb) g_boff[t] = s[t] - v;
}

__global__ void k_scan3(const int* __restrict__ batch, int n, int E) {
    int i = blockIdx.x * blockDim.x + threadIdx.x;
    if (i >= n) return;
    int o = g_off[i] + g_boff[i >> 10];
    g_off[i] = o;
    g_cur[i] = o;
    if (i == 0) g_off[n] = E;
    int b = batch[i];
    int p = (i == 0) ? -1 : batch[i - 1];
    for (int g = p + 1; g <= b; ++g) g_gs[g] = i;
    if (i == n - 1)
        for (int g = b + 1; g <= G_NUM; ++g) g_gs[g] = n;
}

__global__ void k_place(const int* __restrict__ row,
                        const int* __restrict__ col,
                        const float* __restrict__ ew, int E) {
    int e = blockIdx.x * blockDim.x + threadIdx.x;
    if (e >= E) return;
    int r = row[e];
    int c = col[e];
    float nm = g_dis[r] * ew[e];
    int pos = atomicAdd(&g_cur[c], 1);
    g_edge[pos] = make_float2(__int_as_float(r), nm);
}

// ---------------- GEMM: g_hb[n][HID] = bf16( X[n][K] @ W[K][HID] ) ----------------
// 256 thr/CTA, 128 rows/CTA. x staged cooperatively in smem (K-chunks of 32,
// padded stride 36), W chunk staged too. Thread: 4 rows (rg+32i) x 8 cols via
// fp32x2 FMA -> FMA-issue-bound, L1tex light.
template<int K, bool SRC_ACC>
__global__ void __launch_bounds__(256) k_gemm(const float* __restrict__ X,
                                              const float* __restrict__ W, int n) {
    constexpr int KCH = 32;
    constexpr int SXS = KCH + 4;                 // 36-float padded row stride
    __shared__ float sx[128 * SXS];
    __shared__ float sw[KCH * HID];
    const int t = threadIdx.x;
    const int row0 = blockIdx.x * 128;
    const int hq  = (t & 7) * 8;                 // col start (floats)
    const int rg  = t >> 3;                      // 0..31

    u64 acc[4][4];
    #pragma unroll
    for (int i = 0; i < 4; i++)
        #pragma unroll
        for (int j = 0; j < 4; j++) acc[i][j] = 0;

    #pragma unroll
    for (int ch = 0; ch < K / KCH; ch++) {
        if (ch) __syncthreads();
        // stage x chunk: 128 rows x 32 floats, each element loaded once, coalesced
        #pragma unroll
        for (int i = t; i < 128 * (KCH / 4); i += 256) {
            const int r = i >> 3, c = i & 7;
            const int gr = min(row0 + r, n - 1);
            const float* src = (SRC_ACC ? g_acc : X) + (size_t)gr * K + ch * KCH + c * 4;
            float4 v = *(const float4*)src;
            if (SRC_ACC) {
                v.x = fmaxf(v.x, 0.f); v.y = fmaxf(v.y, 0.f);
                v.z = fmaxf(v.z, 0.f); v.w = fmaxf(v.w, 0.f);
            }
            *(float4*)(sx + r * SXS + c * 4) = v;
        }
        // stage w chunk: KCH x HID
        #pragma unroll
        for (int i = t; i < KCH * HID / 4; i += 256)
            ((float4*)sw)[i] = ((const float4*)(W + (size_t)ch * KCH * HID))[i];
        __syncthreads();

        #pragma unroll
        for (int qd = 0; qd < KCH / 4; qd++) {
            float4 xr[4];
            #pragma unroll
            for (int i = 0; i < 4; i++)
                xr[i] = *(const float4*)(sx + (rg + 32 * i) * SXS + qd * 4);
            #pragma unroll
            for (int kk = 0; kk < 4; kk++) {
                const float4 w0 = *(const float4*)(sw + (qd * 4 + kk) * HID + hq);
                const float4 w1 = *(const float4*)(sw + (qd * 4 + kk) * HID + hq + 4);
                const u64 wp0 = pack2(w0.x, w0.y);
                const u64 wp1 = pack2(w0.z, w0.w);
                const u64 wp2 = pack2(w1.x, w1.y);
                const u64 wp3 = pack2(w1.z, w1.w);
                #pragma unroll
                for (int i = 0; i < 4; i++) {
                    const float xv = ((const float*)&xr[i])[kk];
                    const u64 xp = pack2(xv, xv);
                    acc[i][0] = ffma2(xp, wp0, acc[i][0]);
                    acc[i][1] = ffma2(xp, wp1, acc[i][1]);
                    acc[i][2] = ffma2(xp, wp2, acc[i][2]);
                    acc[i][3] = ffma2(xp, wp3, acc[i][3]);
                }
            }
        }
    }

    // store bf16x2
    #pragma unroll
    for (int i = 0; i < 4; i++) {
        const int gr = row0 + rg + 32 * i;
        if (gr < n) {
            uint4 o;
            float2 f0 = unpack2(acc[i][0]); o.x = cvt_bf16x2(f0.x, f0.y);
            float2 f1 = unpack2(acc[i][1]); o.y = cvt_bf16x2(f1.x, f1.y);
            float2 f2 = unpack2(acc[i][2]); o.z = cvt_bf16x2(f2.x, f2.y);
            float2 f3 = unpack2(acc[i][3]); o.w = cvt_bf16x2(f3.x, f3.y);
            *(uint4*)(g_hb + (size_t)gr * (HID / 2) + (t & 7) * 4) = o;
        }
    }
}

// ---------------- per-node CSR gather (bf16 h) ----------------
// 8 lanes/node, lane owns 8 cols (one uint4 of bf16x2 per edge = 16B).
// out = bias + dis^2*h[self] + dis[node] * sum_e (dis[row_e]*ew_e) * h[row_e]
__global__ void k_gather(const float* __restrict__ b, int n) {
    int tid = blockIdx.x * blockDim.x + threadIdx.x;
    int node = tid >> 3;
    if (node >= n) return;
    const int q = tid & 7;

    int e = g_off[node];
    const int e_end = g_off[node + 1];

    u64 a0 = 0, a1 = 0, a2 = 0, a3 = 0;

    for (; e + 3 < e_end; e += 4) {
        float2 rA = g_edge[e];
        float2 rB = g_edge[e + 1];
        float2 rC = g_edge[e + 2];
        float2 rD = g_edge[e + 3];
        uint4 hA = *(const uint4*)(g_hb + (size_t)__float_as_int(rA.x) * (HID / 2) + q * 4);
        uint4 hB = *(const uint4*)(g_hb + (size_t)__float_as_int(rB.x) * (HID / 2) + q * 4);
        uint4 hC = *(const uint4*)(g_hb + (size_t)__float_as_int(rC.x) * (HID / 2) + q * 4);
        uint4 hD = *(const uint4*)(g_hb + (size_t)__float_as_int(rD.x) * (HID / 2) + q * 4);
        const u64 nA = pack2(rA.y, rA.y), nB = pack2(rB.y, rB.y);
        const u64 nC = pack2(rC.y, rC.y), nD = pack2(rD.y, rD.y);
        a0 = ffma2(nA, bf2f2(hA.x), a0); a1 = ffma2(nA, bf2f2(hA.y), a1);
        a2 = ffma2(nA, bf2f2(hA.z), a2); a3 = ffma2(nA, bf2f2(hA.w), a3);
        a0 = ffma2(nB, bf2f2(hB.x), a0); a1 = ffma2(nB, bf2f2(hB.y), a1);
        a2 = ffma2(nB, bf2f2(hB.z), a2); a3 = ffma2(nB, bf2f2(hB.w), a3);
        a0 = ffma2(nC, bf2f2(hC.x), a0); a1 = ffma2(nC, bf2f2(hC.y), a1);
        a2 = ffma2(nC, bf2f2(hC.z), a2); a3 = ffma2(nC, bf2f2(hC.w), a3);
        a0 = ffma2(nD, bf2f2(hD.x), a0); a1 = ffma2(nD, bf2f2(hD.y), a1);
        a2 = ffma2(nD, bf2f2(hD.z), a2); a3 = ffma2(nD, bf2f2(hD.w), a3);
    }
    for (; e < e_end; e++) {
        float2 r0 = g_edge[e];
        uint4 h0 = *(const uint4*)(g_hb + (size_t)__float_as_int(r0.x) * (HID / 2) + q * 4);
        const u64 n0 = pack2(r0.y, r0.y);
        a0 = ffma2(n0, bf2f2(h0.x), a0); a1 = ffma2(n0, bf2f2(h0.y), a1);
        a2 = ffma2(n0, bf2f2(h0.z), a2); a3 = ffma2(n0, bf2f2(h0.w), a3);
    }

    const float d  = g_dis[node];
    const float dd = d * d;
    const uint4 hs = *(const uint4*)(g_hb + (size_t)node * (HID / 2) + q * 4);
    const float* bb = b + q * 8;
    float out[8];
    u64 aa[4] = {a0, a1, a2, a3};
    u32 hh[4] = {hs.x, hs.y, hs.z, hs.w};
    #pragma unroll
    for (int j = 0; j < 4; j++) {
        float2 s = unpack2(bf2f2(hh[j]));
        float2 ev = unpack2(aa[j]);
        out[2*j]   = bb[2*j]   + dd * s.x + d * ev.x;
        out[2*j+1] = bb[2*j+1] + dd * s.y + d * ev.y;
    }
    float* dst = g_acc + (size_t)node * HID + q * 8;
    *(float4*)(dst)     = make_float4(out[0], out[1], out[2], out[3]);
    *(float4*)(dst + 4) = make_float4(out[4], out[5], out[6], out[7]);
}

// ---------------- pool + head ----------------
__global__ void k_pool(int n) {
    const int g = blockIdx.x;
    const int t = threadIdx.x;
    const int q = t & 15;
    const int sub = t >> 4;
    const int s = g_gs[g], e = g_gs[g + 1];

    float4 acc = make_float4(0.f, 0.f, 0.f, 0.f);
    for (int i = s + sub; i < e; i += 16) {
        float4 v = ((const float4*)(g_acc + (size_t)i * HID))[q];
        acc.x += fmaxf(v.x, 0.f); acc.y += fmaxf(v.y, 0.f);
        acc.z += fmaxf(v.z, 0.f); acc.w += fmaxf(v.w, 0.f);
    }
    __shared__ float4 sm[256];
    sm[t] = acc;
    __syncthreads();
    if (sub == 0) {
        float4 a = acc;
        #pragma unroll
        for (int k = 1; k < 16; k++) {
            float4 bb = sm[k * 16 + q];
            a.x += bb.x; a.y += bb.y; a.z += bb.z; a.w += bb.w;
        }
        ((float4*)(g_sums + g * HID))[q] = a;
        if (q == 0) g_gcnt[g] = e - s;
    }
}

__global__ void k_final(const float* __restrict__ Wc,
                        const float* __restrict__ bc,
                        float* __restrict__ out) {
    int g = blockIdx.x * blockDim.x + threadIdx.x;
    if (g >= G_NUM) return;
    const float c = fmaxf((float)g_gcnt[g], 1.0f);
    float acc = 0.0f;
    #pragma unroll
    for (int h = 0; h < HID; h++)
        acc += g_sums[g * HID + h] * Wc[h];
    out[g] = acc / c + bc[0];
}

// ---------------- launcher ----------------
extern "C" void kernel_launch(void* const* d_in, const int* in_sizes, int n_in,
                              void* d_out, int out_size) {
    const float* x     = (const float*)d_in[0];
    const int*   ei    = (const int*)  d_in[1];   // int32 (JAX x64 disabled)
    const float* ew    = (const float*)d_in[2];
    const int*   batch = (const int*)  d_in[3];
    const float* W1    = (const float*)d_in[4];
    const float* b1    = (const float*)d_in[5];
    const float* W2    = (const float*)d_in[6];
    const float* b2    = (const float*)d_in[7];
    const float* Wc    = (const float*)d_in[8];
    const float* bc    = (const float*)d_in[9];
    float* out = (float*)d_out;

    const int n = in_sizes[0] / IN_DIM;   // 100000
    const int E = in_sizes[2];            // 3200000
    const int* row = ei;
    const int* col = ei + E;
    const int T = 256;
    const int nb = (n + SCAN_B - 1) / SCAN_B;

    k_reset<<<(n + T - 1) / T, T>>>(n);
    k_deg  <<<(E + T - 1) / T, T>>>(col, ew, E);
    k_scan1<<<nb, SCAN_B>>>(n);
    k_gemm<IN_DIM, false><<<(n + 127) / 128, T>>>(x, W1, n);   // independent of scan chain
    k_scan2<<<1, 128>>>(nb);
    k_scan3<<<(n + T - 1) / T, T>>>(batch, n, E);
    k_place<<<(E + T - 1) / T, T>>>(row, col, ew, E);

    k_gather<<<(n * 8 + T - 1) / T, T>>>(b1, n);               // layer 1

    k_gemm<HID, true><<<(n + 127) / 128, T>>>(nullptr, W2, n); // layer 2
    k_gather<<<(n * 8 + T - 1) / T, T>>>(b2, n);

    k_pool <<<G_NUM, 256>>>(n);
    k_final<<<1, T>>>(Wc, bc, out);
}

// round 11
// speedup vs baseline: 1.1949x; 1.0432x over previous
#include <cuda_runtime.h>

#define MAXN   100000
#define MAXE   3200000
#define IN_DIM 128
#define HID    64
#define G_NUM  256
#define SCAN_B 1024

typedef unsigned long long u64;
typedef unsigned int u32;

// ---- packed fp32x2 helpers (sm_100+) ----
__device__ __forceinline__ u64 pack2(float lo, float hi) {
    u64 r; asm("mov.b64 %0, {%1, %2};" : "=l"(r) : "f"(lo), "f"(hi)); return r;
}
__device__ __forceinline__ u64 ffma2(u64 a, u64 b, u64 c) {
    u64 d; asm("fma.rn.f32x2 %0, %1, %2, %3;" : "=l"(d) : "l"(a), "l"(b), "l"(c)); return d;
}
__device__ __forceinline__ float2 unpack2(u64 v) {
    float2 f; asm("mov.b64 {%0, %1}, %2;" : "=f"(f.x), "=f"(f.y) : "l"(v)); return f;
}
__device__ __forceinline__ u32 cvt_bf16x2(float lo, float hi) {
    u32 r; asm("cvt.rn.bf16x2.f32 %0, %1, %2;" : "=r"(r) : "f"(hi), "f"(lo)); return r;
}
__device__ __forceinline__ u64 bf2f2(u32 u) {
    u32 lo = u << 16;
    u32 hi = u & 0xFFFF0000u;
    u64 r; asm("mov.b64 %0, {%1, %2};" : "=l"(r) : "r"(lo), "r"(hi)); return r;
}
// ---- cp.async helpers ----
__device__ __forceinline__ void cp16(void* sdst, const void* gsrc) {
    u32 s = (u32)__cvta_generic_to_shared(sdst);
    asm volatile("cp.async.cg.shared.global [%0], [%1], 16;" :: "r"(s), "l"(gsrc) : "memory");
}
__device__ __forceinline__ void cp_commit() {
    asm volatile("cp.async.commit_group;" ::: "memory");
}
template<int N>
__device__ __forceinline__ void cp_wait() {
    asm volatile("cp.async.wait_group %0;" :: "n"(N) : "memory");
}

// ---------------- device scratch (no allocation allowed) ----------------
__device__ __align__(16) u32   g_hb [MAXN * (size_t)(HID / 2)]; // bf16x2 GEMM output
__device__ __align__(16) float g_acc[MAXN * (size_t)HID];       // relu'd layer output (f32)
__device__ __align__(16) float2 g_edge[MAXE];                   // {row bits, dis[row]*ew}
__device__ float g_deg [MAXN];
__device__ float g_dis [MAXN];
__device__ int   g_cntn[MAXN];
__device__ int   g_off [MAXN + 1];
__device__ int   g_cur [MAXN];
__device__ int   g_bsum[(MAXN + SCAN_B - 1) / SCAN_B];
__device__ int   g_boff[(MAXN + SCAN_B - 1) / SCAN_B];
__device__ int   g_gs  [G_NUM + 1];
__device__ int   g_gcnt[G_NUM];
__device__ __align__(16) float g_sums[G_NUM * HID];

// ---------------- prolog kernels ----------------

__global__ void k_reset(int n) {
    int i = blockIdx.x * blockDim.x + threadIdx.x;
    if (i < n) { g_deg[i] = 1.0f; g_cntn[i] = 0; }
}

__global__ void k_deg(const int* __restrict__ col,
                      const float* __restrict__ ew, int E) {
    int e = blockIdx.x * blockDim.x + threadIdx.x;
    if (e < E) {
        int c = col[e];
        atomicAdd(&g_deg[c], ew[e]);
        atomicAdd(&g_cntn[c], 1);
    }
}

__global__ void k_scan1(int n) {
    __shared__ int s[2][SCAN_B];
    const int t = threadIdx.x;
    const int i = blockIdx.x * SCAN_B + t;
    if (i < n) g_dis[i] = rsqrtf(g_deg[i]);
    int v = (i < n) ? g_cntn[i] : 0;
    s[0][t] = v;
    __syncthreads();
    int src = 0;
    #pragma unroll
    for (int d = 1; d < SCAN_B; d <<= 1) {
        int x = s[src][t];
        if (t >= d) x += s[src][t - d];
        s[1 - src][t] = x;
        src = 1 - src;
        __syncthreads();
    }
    int incl = s[src][t];
    if (i < n) g_off[i] = incl - v;
    if (t == SCAN_B - 1) g_bsum[blockIdx.x] = incl;
}

__global__ void k_scan2(int nb) {
    __shared__ int s[128];
    const int t = threadIdx.x;
    int v = (t < nb) ? g_bsum[t] : 0;
    s[t] = v;
    __syncthreads();
    #pragma unroll
    for (int d = 1; d < 128; d <<= 1) {
        int x = s[t];
        if (t >= d) x += s[t - d];
        __syncthreads();
        s[t] = x;
        __syncthreads();
    }
    if (t < nb) g_boff[t] = s[t] - v;
}

__global__ void k_scan3(const int* __restrict__ batch, int n, int E) {
    int i = blockIdx.x * blockDim.x + threadIdx.x;
    if (i >= n) return;
    int o = g_off[i] + g_boff[i >> 10];
    g_off[i] = o;
    g_cur[i] = o;
    if (i == 0) g_off[n] = E;
    int b = batch[i];
    int p = (i == 0) ? -1 : batch[i - 1];
    for (int g = p + 1; g <= b; ++g) g_gs[g] = i;
    if (i == n - 1)
        for (int g = b + 1; g <= G_NUM; ++g) g_gs[g] = n;
}

__global__ void k_place(const int* __restrict__ row,
                        const int* __restrict__ col,
                        const float* __restrict__ ew, int E) {
    int e = blockIdx.x * blockDim.x + threadIdx.x;
    if (e >= E) return;
    int r = row[e];
    int c = col[e];
    float nm = g_dis[r] * ew[e];
    int pos = atomicAdd(&g_cur[c], 1);
    g_edge[pos] = make_float2(__int_as_float(r), nm);
}

// ---------------- GEMM: g_hb[n][HID] = bf16( X[n][K] @ W[K][HID] ) ----------------
// 256 thr/CTA, 128 rows/CTA. cp.async double-buffered K-chunks of 16 so DRAM/L2
// latency overlaps FFMA2 work. Thread: 4 rows (rg+32i) x 8 cols.
// SRC_ACC input (g_acc) is already relu'd by k_gather.
template<int K, bool SRC_ACC>
__global__ void __launch_bounds__(256) k_gemm(const float* __restrict__ X,
                                              const float* __restrict__ W, int n) {
    constexpr int KCH = 16;
    constexpr int SXS = KCH + 4;                 // 20-float padded row stride
    constexpr int NCH = K / KCH;
    __shared__ float sx[2][128 * SXS];
    __shared__ float sw[2][KCH * HID];
    const int t = threadIdx.x;
    const int row0 = blockIdx.x * 128;
    const int hq  = (t & 7) * 8;                 // col start (floats)
    const int rg  = t >> 3;                      // 0..31
    const float* xbase = SRC_ACC ? g_acc : X;

    // stage one chunk into buffer buf (x: 2 cp16/thread, w: 1 cp16/thread)
    auto stage = [&](int ch, int buf) {
        #pragma unroll
        for (int i = t; i < 128 * (KCH / 4); i += 256) {
            const int r = i >> 2, c = i & 3;
            const int gr = min(row0 + r, n - 1);
            cp16(&sx[buf][r * SXS + c * 4],
                 xbase + (size_t)gr * K + ch * KCH + c * 4);
        }
        cp16(&sw[buf][t * 4], W + (size_t)ch * KCH * HID + t * 4);
        cp_commit();
    };

    u64 acc[4][4];
    #pragma unroll
    for (int i = 0; i < 4; i++)
        #pragma unroll
        for (int j = 0; j < 4; j++) acc[i][j] = 0;

    stage(0, 0);
    #pragma unroll
    for (int ch = 0; ch < NCH; ch++) {
        const int buf = ch & 1;
        if (ch + 1 < NCH) { stage(ch + 1, buf ^ 1); cp_wait<1>(); }
        else             { cp_wait<0>(); }
        __syncthreads();

        #pragma unroll
        for (int qd = 0; qd < KCH / 4; qd++) {
            float4 xr[4];
            #pragma unroll
            for (int i = 0; i < 4; i++)
                xr[i] = *(const float4*)(&sx[buf][(rg + 32 * i) * SXS + qd * 4]);
            #pragma unroll
            for (int kk = 0; kk < 4; kk++) {
                const float4 w0 = *(const float4*)(&sw[buf][(qd * 4 + kk) * HID + hq]);
                const float4 w1 = *(const float4*)(&sw[buf][(qd * 4 + kk) * HID + hq + 4]);
                const u64 wp0 = pack2(w0.x, w0.y);
                const u64 wp1 = pack2(w0.z, w0.w);
                const u64 wp2 = pack2(w1.x, w1.y);
                const u64 wp3 = pack2(w1.z, w1.w);
                #pragma unroll
                for (int i = 0; i < 4; i++) {
                    const float xv = ((const float*)&xr[i])[kk];
                    const u64 xp = pack2(xv, xv);
                    acc[i][0] = ffma2(xp, wp0, acc[i][0]);
                    acc[i][1] = ffma2(xp, wp1, acc[i][1]);
                    acc[i][2] = ffma2(xp, wp2, acc[i][2]);
                    acc[i][3] = ffma2(xp, wp3, acc[i][3]);
                }
            }
        }
        __syncthreads();   // protect buffer reuse before next prefetch lands
    }

    #pragma unroll
    for (int i = 0; i < 4; i++) {
        const int gr = row0 + rg + 32 * i;
        if (gr < n) {
            uint4 o;
            float2 f0 = unpack2(acc[i][0]); o.x = cvt_bf16x2(f0.x, f0.y);
            float2 f1 = unpack2(acc[i][1]); o.y = cvt_bf16x2(f1.x, f1.y);
            float2 f2 = unpack2(acc[i][2]); o.z = cvt_bf16x2(f2.x, f2.y);
            float2 f3 = unpack2(acc[i][3]); o.w = cvt_bf16x2(f3.x, f3.y);
            *(uint4*)(g_hb + (size_t)gr * (HID / 2) + (t & 7) * 4) = o;
        }
    }
}

// ---------------- per-node CSR gather (bf16 h), relu applied at store ----------------
// 8 lanes/node, lane owns 8 cols (one uint4 of bf16x2 per edge = 16B).
// g_acc = relu( bias + dis^2*h[self] + dis * sum_e (dis[row_e]*ew_e) * h[row_e] )
__global__ void k_gather(const float* __restrict__ b, int n) {
    int tid = blockIdx.x * blockDim.x + threadIdx.x;
    int node = tid >> 3;
    if (node >= n) return;
    const int q = tid & 7;

    int e = g_off[node];
    const int e_end = g_off[node + 1];

    u64 a0 = 0, a1 = 0, a2 = 0, a3 = 0;

    for (; e + 3 < e_end; e += 4) {
        float2 rA = g_edge[e];
        float2 rB = g_edge[e + 1];
        float2 rC = g_edge[e + 2];
        float2 rD = g_edge[e + 3];
        uint4 hA = *(const uint4*)(g_hb + (size_t)__float_as_int(rA.x) * (HID / 2) + q * 4);
        uint4 hB = *(const uint4*)(g_hb + (size_t)__float_as_int(rB.x) * (HID / 2) + q * 4);
        uint4 hC = *(const uint4*)(g_hb + (size_t)__float_as_int(rC.x) * (HID / 2) + q * 4);
        uint4 hD = *(const uint4*)(g_hb + (size_t)__float_as_int(rD.x) * (HID / 2) + q * 4);
        const u64 nA = pack2(rA.y, rA.y), nB = pack2(rB.y, rB.y);
        const u64 nC = pack2(rC.y, rC.y), nD = pack2(rD.y, rD.y);
        a0 = ffma2(nA, bf2f2(hA.x), a0); a1 = ffma2(nA, bf2f2(hA.y), a1);
        a2 = ffma2(nA, bf2f2(hA.z), a2); a3 = ffma2(nA, bf2f2(hA.w), a3);
        a0 = ffma2(nB, bf2f2(hB.x), a0); a1 = ffma2(nB, bf2f2(hB.y), a1);
        a2 = ffma2(nB, bf2f2(hB.z), a2); a3 = ffma2(nB, bf2f2(hB.w), a3);
        a0 = ffma2(nC, bf2f2(hC.x), a0); a1 = ffma2(nC, bf2f2(hC.y), a1);
        a2 = ffma2(nC, bf2f2(hC.z), a2); a3 = ffma2(nC, bf2f2(hC.w), a3);
        a0 = ffma2(nD, bf2f2(hD.x), a0); a1 = ffma2(nD, bf2f2(hD.y), a1);
        a2 = ffma2(nD, bf2f2(hD.z), a2); a3 = ffma2(nD, bf2f2(hD.w), a3);
    }
    for (; e < e_end; e++) {
        float2 r0 = g_edge[e];
        uint4 h0 = *(const uint4*)(g_hb + (size_t)__float_as_int(r0.x) * (HID / 2) + q * 4);
        const u64 n0 = pack2(r0.y, r0.y);
        a0 = ffma2(n0, bf2f2(h0.x), a0); a1 = ffma2(n0, bf2f2(h0.y), a1);
        a2 = ffma2(n0, bf2f2(h0.z), a2); a3 = ffma2(n0, bf2f2(h0.w), a3);
    }

    const float d  = g_dis[node];
    const float dd = d * d;
    const uint4 hs = *(const uint4*)(g_hb + (size_t)node * (HID / 2) + q * 4);
    const float* bb = b + q * 8;
    float out[8];
    u64 aa[4] = {a0, a1, a2, a3};
    u32 hh[4] = {hs.x, hs.y, hs.z, hs.w};
    #pragma unroll
    for (int j = 0; j < 4; j++) {
        float2 s = unpack2(bf2f2(hh[j]));
        float2 ev = unpack2(aa[j]);
        out[2*j]   = fmaxf(bb[2*j]   + dd * s.x + d * ev.x, 0.0f);
        out[2*j+1] = fmaxf(bb[2*j+1] + dd * s.y + d * ev.y, 0.0f);
    }
    float* dst = g_acc + (size_t)node * HID + q * 8;
    *(float4*)(dst)     = make_float4(out[0], out[1], out[2], out[3]);
    *(float4*)(dst + 4) = make_float4(out[4], out[5], out[6], out[7]);
}

// ---------------- pool + head (g_acc already relu'd) ----------------
__global__ void k_pool(int n) {
    const int g = blockIdx.x;
    const int t = threadIdx.x;
    const int q = t & 15;
    const int sub = t >> 4;
    const int s = g_gs[g], e = g_gs[g + 1];

    float4 acc = make_float4(0.f, 0.f, 0.f, 0.f);
    for (int i = s + sub; i < e; i += 16) {
        float4 v = ((const float4*)(g_acc + (size_t)i * HID))[q];
        acc.x += v.x; acc.y += v.y; acc.z += v.z; acc.w += v.w;
    }
    __shared__ float4 sm[256];
    sm[t] = acc;
    __syncthreads();
    if (sub == 0) {
        float4 a = acc;
        #pragma unroll
        for (int k = 1; k < 16; k++) {
            float4 bb = sm[k * 16 + q];
            a.x += bb.x; a.y += bb.y; a.z += bb.z; a.w += bb.w;
        }
        ((float4*)(g_sums + g * HID))[q] = a;
        if (q == 0) g_gcnt[g] = e - s;
    }
}

__global__ void k_final(const float* __restrict__ Wc,
                        const float* __restrict__ bc,
                        float* __restrict__ out) {
    int g = blockIdx.x * blockDim.x + threadIdx.x;
    if (g >= G_NUM) return;
    const float c = fmaxf((float)g_gcnt[g], 1.0f);
    float acc = 0.0f;
    #pragma unroll
    for (int h = 0; h < HID; h++)
        acc += g_sums[g * HID + h] * Wc[h];
    out[g] = acc / c + bc[0];
}

// ---------------- launcher ----------------
extern "C" void kernel_launch(void* const* d_in, const int* in_sizes, int n_in,
                              void* d_out, int out_size) {
    const float* x     = (const float*)d_in[0];
    const int*   ei    = (const int*)  d_in[1];   // int32 (JAX x64 disabled)
    const float* ew    = (const float*)d_in[2];
    const int*   batch = (const int*)  d_in[3];
    const float* W1    = (const float*)d_in[4];
    const float* b1    = (const float*)d_in[5];
    const float* W2    = (const float*)d_in[6];
    const float* b2    = (const float*)d_in[7];
    const float* Wc    = (const float*)d_in[8];
    const float* bc    = (const float*)d_in[9];
    float* out = (float*)d_out;

    const int n = in_sizes[0] / IN_DIM;   // 100000
    const int E = in_sizes[2];            // 3200000
    const int* row = ei;
    const int* col = ei + E;
    const int T = 256;
    const int nb = (n + SCAN_B - 1) / SCAN_B;

    k_reset<<<(n + T - 1) / T, T>>>(n);
    k_deg  <<<(E + T - 1) / T, T>>>(col, ew, E);
    k_scan1<<<nb, SCAN_B>>>(n);
    k_gemm<IN_DIM, false><<<(n + 127) / 128, T>>>(x, W1, n);   // independent of scan chain
    k_scan2<<<1, 128>>>(nb);
    k_scan3<<<(n + T - 1) / T, T>>>(batch, n, E);
    k_place<<<(E + T - 1) / T, T>>>(row, col, ew, E);

    k_gather<<<(n * 8 + T - 1) / T, T>>>(b1, n);               // layer 1

    k_gemm<HID, true><<<(n + 127) / 128, T>>>(nullptr, W2, n); // layer 2
    k_gather<<<(n * 8 + T - 1) / T, T>>>(b2, n);

    k_pool <<<G_NUM, 256>>>(n);
    k_final<<<1, T>>>(Wc, bc, out);
}

// round 12
// speedup vs baseline: 1.3812x; 1.1559x over previous
#include <cuda_runtime.h>

#define MAXN   100000
#define MAXE   3200000
#define IN_DIM 128
#define HID    64
#define G_NUM  256
#define SCAN_B 1024

typedef unsigned long long u64;
typedef unsigned int u32;

// ---- packed fp32x2 helpers (sm_100+) ----
__device__ __forceinline__ u64 pack2(float lo, float hi) {
    u64 r; asm("mov.b64 %0, {%1, %2};" : "=l"(r) : "f"(lo), "f"(hi)); return r;
}
__device__ __forceinline__ u64 ffma2(u64 a, u64 b, u64 c) {
    u64 d; asm("fma.rn.f32x2 %0, %1, %2, %3;" : "=l"(d) : "l"(a), "l"(b), "l"(c)); return d;
}
__device__ __forceinline__ float2 unpack2(u64 v) {
    float2 f; asm("mov.b64 {%0, %1}, %2;" : "=f"(f.x), "=f"(f.y) : "l"(v)); return f;
}
__device__ __forceinline__ u32 cvt_bf16x2(float lo, float hi) {
    u32 r; asm("cvt.rn.bf16x2.f32 %0, %1, %2;" : "=r"(r) : "f"(hi), "f"(lo)); return r;
}
__device__ __forceinline__ u64 bf2f2(u32 u) {
    u32 lo = u << 16;
    u32 hi = u & 0xFFFF0000u;
    u64 r; asm("mov.b64 %0, {%1, %2};" : "=l"(r) : "r"(lo), "r"(hi)); return r;
}
// ---- cp.async helpers ----
__device__ __forceinline__ void cp16(void* sdst, const void* gsrc) {
    u32 s = (u32)__cvta_generic_to_shared(sdst);
    asm volatile("cp.async.cg.shared.global [%0], [%1], 16;" :: "r"(s), "l"(gsrc) : "memory");
}
__device__ __forceinline__ void cp_commit() {
    asm volatile("cp.async.commit_group;" ::: "memory");
}
template<int N>
__device__ __forceinline__ void cp_wait() {
    asm volatile("cp.async.wait_group %0;" :: "n"(N) : "memory");
}

// ---------------- device scratch (no allocation allowed) ----------------
__device__ __align__(16) u32   g_hb [MAXN * (size_t)(HID / 2)]; // bf16x2 GEMM output
__device__ __align__(16) float g_acc[MAXN * (size_t)HID];       // relu'd layer output (f32)
__device__ __align__(16) float2 g_edge[MAXE];                   // {row bits, dis[row]*ew}
__device__ float g_deg [MAXN];
__device__ float g_dis [MAXN];
__device__ int   g_cntn[MAXN];
__device__ int   g_off [MAXN + 1];
__device__ int   g_cur [MAXN];
__device__ int   g_bsum[(MAXN + SCAN_B - 1) / SCAN_B];
__device__ int   g_boff[(MAXN + SCAN_B - 1) / SCAN_B];
__device__ int   g_gs  [G_NUM + 1];
__device__ int   g_gcnt[G_NUM];
__device__ __align__(16) float g_sums[G_NUM * HID];

// ================= GEMM body (device function; callable from fused kernels) ==
// g_hb[row0..row0+128][HID] = bf16( X[.][K] @ W[K][HID] )
// 3-stage cp.async pipeline, KCH=16, one __syncthreads per chunk.
// W smem tile: upper 32 cols offset +4 words -> conflict-free 8-lane reads.
template<int K, bool SRC_ACC>
__device__ __forceinline__ void gemm_body(const float* __restrict__ X,
                                          const float* __restrict__ W,
                                          int n, int bid) {
    constexpr int KCH = 16;
    constexpr int SXS = KCH + 4;                 // 20-float padded x row stride
    constexpr int SWS = HID + 4;                 // 68-float w row stride
    constexpr int NCH = K / KCH;
    __shared__ float sx[3][128 * SXS];
    __shared__ float sw[3][KCH * SWS];
    const int t = threadIdx.x;
    const int row0 = bid * 128;
    const int hq  = (t & 7) * 8;                 // col start (floats)
    const int hqs = hq + ((t & 7) >> 2) * 4;     // bank-shifted smem col
    const int rg  = t >> 3;                      // 0..31
    const float* xbase = SRC_ACC ? g_acc : X;

    auto stage = [&](int ch, int buf) {
        #pragma unroll
        for (int i = t; i < 128 * (KCH / 4); i += 256) {
            const int r = i >> 2, c = i & 3;
            const int gr = min(row0 + r, n - 1);
            cp16(&sx[buf][r * SXS + c * 4],
                 xbase + (size_t)gr * K + ch * KCH + c * 4);
        }
        {   // 256 float4 of W per chunk: one per thread
            const int k = t >> 4, c4 = t & 15;
            cp16(&sw[buf][k * SWS + c4 * 4 + (c4 >= 8 ? 4 : 0)],
                 W + (size_t)(ch * KCH + k) * HID + c4 * 4);
        }
        cp_commit();
    };

    u64 acc[4][4];
    #pragma unroll
    for (int i = 0; i < 4; i++)
        #pragma unroll
        for (int j = 0; j < 4; j++) acc[i][j] = 0;

    stage(0, 0);
    stage(1, 1);
    #pragma unroll
    for (int ch = 0; ch < NCH; ch++) {
        const int buf = ch % 3;
        if (ch + 1 < NCH) cp_wait<1>(); else cp_wait<0>();
        __syncthreads();
        if (ch + 2 < NCH) stage(ch + 2, (ch + 2) % 3);

        #pragma unroll
        for (int qd = 0; qd < KCH / 4; qd++) {
            float4 xr[4];
            #pragma unroll
            for (int i = 0; i < 4; i++)
                xr[i] = *(const float4*)(&sx[buf][(rg + 32 * i) * SXS + qd * 4]);
            #pragma unroll
            for (int kk = 0; kk < 4; kk++) {
                const float* wrow = &sw[buf][(qd * 4 + kk) * SWS];
                const float4 w0 = *(const float4*)(wrow + hqs);
                const float4 w1 = *(const float4*)(wrow + hqs + 4);
                const u64 wp0 = pack2(w0.x, w0.y);
                const u64 wp1 = pack2(w0.z, w0.w);
                const u64 wp2 = pack2(w1.x, w1.y);
                const u64 wp3 = pack2(w1.z, w1.w);
                #pragma unroll
                for (int i = 0; i < 4; i++) {
                    const float xv = ((const float*)&xr[i])[kk];
                    const u64 xp = pack2(xv, xv);
                    acc[i][0] = ffma2(xp, wp0, acc[i][0]);
                    acc[i][1] = ffma2(xp, wp1, acc[i][1]);
                    acc[i][2] = ffma2(xp, wp2, acc[i][2]);
                    acc[i][3] = ffma2(xp, wp3, acc[i][3]);
                }
            }
        }
    }

    #pragma unroll
    for (int i = 0; i < 4; i++) {
        const int gr = row0 + rg + 32 * i;
        if (gr < n) {
            uint4 o;
            float2 f0 = unpack2(acc[i][0]); o.x = cvt_bf16x2(f0.x, f0.y);
            float2 f1 = unpack2(acc[i][1]); o.y = cvt_bf16x2(f1.x, f1.y);
            float2 f2 = unpack2(acc[i][2]); o.z = cvt_bf16x2(f2.x, f2.y);
            float2 f3 = unpack2(acc[i][3]); o.w = cvt_bf16x2(f3.x, f3.y);
            *(uint4*)(g_hb + (size_t)gr * (HID / 2) + (t & 7) * 4) = o;
        }
    }
}

// ---------------- prolog / fused kernels ----------------

__global__ void k_reset(int n) {
    int i = blockIdx.x * blockDim.x + threadIdx.x;
    if (i < n) { g_deg[i] = 1.0f; g_cntn[i] = 0; }
}

// fused: blocks [0,gB) run GEMM1 rows [0, gB*128); the rest run the degree histogram
__global__ void __launch_bounds__(256) k_deg_gemm1(
    const int* __restrict__ col, const float* __restrict__ ew, int E,
    const float* __restrict__ x, const float* __restrict__ W1, int n, int gB) {
    if ((int)blockIdx.x < gB) {
        gemm_body<IN_DIM, false>(x, W1, n, blockIdx.x);
        return;
    }
    int e = ((int)blockIdx.x - gB) * 256 + threadIdx.x;
    if (e < E) {
        int c = col[e];
        atomicAdd(&g_deg[c], ew[e]);
        atomicAdd(&g_cntn[c], 1);
    }
}

__global__ void k_scan1(int n) {
    __shared__ int s[2][SCAN_B];
    const int t = threadIdx.x;
    const int i = blockIdx.x * SCAN_B + t;
    if (i < n) g_dis[i] = rsqrtf(g_deg[i]);
    int v = (i < n) ? g_cntn[i] : 0;
    s[0][t] = v;
    __syncthreads();
    int src = 0;
    #pragma unroll
    for (int d = 1; d < SCAN_B; d <<= 1) {
        int x = s[src][t];
        if (t >= d) x += s[src][t - d];
        s[1 - src][t] = x;
        src = 1 - src;
        __syncthreads();
    }
    int incl = s[src][t];
    if (i < n) g_off[i] = incl - v;
    if (t == SCAN_B - 1) g_bsum[blockIdx.x] = incl;
}

__global__ void k_scan2(int nb) {
    __shared__ int s[128];
    const int t = threadIdx.x;
    int v = (t < nb) ? g_bsum[t] : 0;
    s[t] = v;
    __syncthreads();
    #pragma unroll
    for (int d = 1; d < 128; d <<= 1) {
        int x = s[t];
        if (t >= d) x += s[t - d];
        __syncthreads();
        s[t] = x;
        __syncthreads();
    }
    if (t < nb) g_boff[t] = s[t] - v;
}

__global__ void k_scan3(const int* __restrict__ batch, int n, int E) {
    int i = blockIdx.x * blockDim.x + threadIdx.x;
    if (i >= n) return;
    int o = g_off[i] + g_boff[i >> 10];
    g_off[i] = o;
    g_cur[i] = o;
    if (i == 0) g_off[n] = E;
    int b = batch[i];
    int p = (i == 0) ? -1 : batch[i - 1];
    for (int g = p + 1; g <= b; ++g) g_gs[g] = i;
    if (i == n - 1)
        for (int g = b + 1; g <= G_NUM; ++g) g_gs[g] = n;
}

// fused: blocks [0,gB) run GEMM1 rows [rowBase*128, ...); the rest place edges
__global__ void __launch_bounds__(256) k_place_gemm1(
    const int* __restrict__ row, const int* __restrict__ col,
    const float* __restrict__ ew, int E,
    const float* __restrict__ x, const float* __restrict__ W1, int n,
    int gB, int rowBase) {
    if ((int)blockIdx.x < gB) {
        gemm_body<IN_DIM, false>(x, W1, n, rowBase + blockIdx.x);
        return;
    }
    int e = ((int)blockIdx.x - gB) * 256 + threadIdx.x;
    if (e >= E) return;
    int r = row[e];
    int c = col[e];
    float nm = g_dis[r] * ew[e];
    int pos = atomicAdd(&g_cur[c], 1);
    g_edge[pos] = make_float2(__int_as_float(r), nm);
}

// standalone GEMM2
__global__ void __launch_bounds__(256) k_gemm2(const float* __restrict__ W, int n) {
    gemm_body<HID, true>(nullptr, W, n, blockIdx.x);
}

// ---------------- per-node CSR gather (bf16 h), relu applied at store --------
__global__ void k_gather(const float* __restrict__ b, int n) {
    int tid = blockIdx.x * blockDim.x + threadIdx.x;
    int node = tid >> 3;
    if (node >= n) return;
    const int q = tid & 7;

    int e = g_off[node];
    const int e_end = g_off[node + 1];

    u64 a0 = 0, a1 = 0, a2 = 0, a3 = 0;

    for (; e + 3 < e_end; e += 4) {
        float2 rA = g_edge[e];
        float2 rB = g_edge[e + 1];
        float2 rC = g_edge[e + 2];
        float2 rD = g_edge[e + 3];
        uint4 hA = *(const uint4*)(g_hb + (size_t)__float_as_int(rA.x) * (HID / 2) + q * 4);
        uint4 hB = *(const uint4*)(g_hb + (size_t)__float_as_int(rB.x) * (HID / 2) + q * 4);
        uint4 hC = *(const uint4*)(g_hb + (size_t)__float_as_int(rC.x) * (HID / 2) + q * 4);
        uint4 hD = *(const uint4*)(g_hb + (size_t)__float_as_int(rD.x) * (HID / 2) + q * 4);
        const u64 nA = pack2(rA.y, rA.y), nB = pack2(rB.y, rB.y);
        const u64 nC = pack2(rC.y, rC.y), nD = pack2(rD.y, rD.y);
        a0 = ffma2(nA, bf2f2(hA.x), a0); a1 = ffma2(nA, bf2f2(hA.y), a1);
        a2 = ffma2(nA, bf2f2(hA.z), a2); a3 = ffma2(nA, bf2f2(hA.w), a3);
        a0 = ffma2(nB, bf2f2(hB.x), a0); a1 = ffma2(nB, bf2f2(hB.y), a1);
        a2 = ffma2(nB, bf2f2(hB.z), a2); a3 = ffma2(nB, bf2f2(hB.w), a3);
        a0 = ffma2(nC, bf2f2(hC.x), a0); a1 = ffma2(nC, bf2f2(hC.y), a1);
        a2 = ffma2(nC, bf2f2(hC.z), a2); a3 = ffma2(nC, bf2f2(hC.w), a3);
        a0 = ffma2(nD, bf2f2(hD.x), a0); a1 = ffma2(nD, bf2f2(hD.y), a1);
        a2 = ffma2(nD, bf2f2(hD.z), a2); a3 = ffma2(nD, bf2f2(hD.w), a3);
    }
    for (; e < e_end; e++) {
        float2 r0 = g_edge[e];
        uint4 h0 = *(const uint4*)(g_hb + (size_t)__float_as_int(r0.x) * (HID / 2) + q * 4);
        const u64 n0 = pack2(r0.y, r0.y);
        a0 = ffma2(n0, bf2f2(h0.x), a0); a1 = ffma2(n0, bf2f2(h0.y), a1);
        a2 = ffma2(n0, bf2f2(h0.z), a2); a3 = ffma2(n0, bf2f2(h0.w), a3);
    }

    const float d  = g_dis[node];
    const float dd = d * d;
    const uint4 hs = *(const uint4*)(g_hb + (size_t)node * (HID / 2) + q * 4);
    const float* bb = b + q * 8;
    float out[8];
    u64 aa[4] = {a0, a1, a2, a3};
    u32 hh[4] = {hs.x, hs.y, hs.z, hs.w};
    #pragma unroll
    for (int j = 0; j < 4; j++) {
        float2 s = unpack2(bf2f2(hh[j]));
        float2 ev = unpack2(aa[j]);
        out[2*j]   = fmaxf(bb[2*j]   + dd * s.x + d * ev.x, 0.0f);
        out[2*j+1] = fmaxf(bb[2*j+1] + dd * s.y + d * ev.y, 0.0f);
    }
    float* dst = g_acc + (size_t)node * HID + q * 8;
    *(float4*)(dst)     = make_float4(out[0], out[1], out[2], out[3]);
    *(float4*)(dst + 4) = make_float4(out[4], out[5], out[6], out[7]);
}

// ---------------- pool + head (g_acc already relu'd) ----------------
__global__ void k_pool(int n) {
    const int g = blockIdx.x;
    const int t = threadIdx.x;
    const int q = t & 15;
    const int sub = t >> 4;
    const int s = g_gs[g], e = g_gs[g + 1];

    float4 acc = make_float4(0.f, 0.f, 0.f, 0.f);
    for (int i = s + sub; i < e; i += 16) {
        float4 v = ((const float4*)(g_acc + (size_t)i * HID))[q];
        acc.x += v.x; acc.y += v.y; acc.z += v.z; acc.w += v.w;
    }
    __shared__ float4 sm[256];
    sm[t] = acc;
    __syncthreads();
    if (sub == 0) {
        float4 a = acc;
        #pragma unroll
        for (int k = 1; k < 16; k++) {
            float4 bb = sm[k * 16 + q];
            a.x += bb.x; a.y += bb.y; a.z += bb.z; a.w += bb.w;
        }
        ((float4*)(g_sums + g * HID))[q] = a;
        if (q == 0) g_gcnt[g] = e - s;
    }
}

__global__ void k_final(const float* __restrict__ Wc,
                        const float* __restrict__ bc,
                        float* __restrict__ out) {
    int g = blockIdx.x * blockDim.x + threadIdx.x;
    if (g >= G_NUM) return;
    const float c = fmaxf((float)g_gcnt[g], 1.0f);
    float acc = 0.0f;
    #pragma unroll
    for (int h = 0; h < HID; h++)
        acc += g_sums[g * HID + h] * Wc[h];
    out[g] = acc / c + bc[0];
}

// ---------------- launcher ----------------
extern "C" void kernel_launch(void* const* d_in, const int* in_sizes, int n_in,
                              void* d_out, int out_size) {
    const float* x     = (const float*)d_in[0];
    const int*   ei    = (const int*)  d_in[1];   // int32 (JAX x64 disabled)
    const float* ew    = (const float*)d_in[2];
    const int*   batch = (const int*)  d_in[3];
    const float* W1    = (const float*)d_in[4];
    const float* b1    = (const float*)d_in[5];
    const float* W2    = (const float*)d_in[6];
    const float* b2    = (const float*)d_in[7];
    const float* Wc    = (const float*)d_in[8];
    const float* bc    = (const float*)d_in[9];
    float* out = (float*)d_out;

    const int n = in_sizes[0] / IN_DIM;   // 100000
    const int E = in_sizes[2];            // 3200000
    const int* row = ei;
    const int* col = ei + E;
    const int T = 256;
    const int nb = (n + SCAN_B - 1) / SCAN_B;
    const int nblk  = (n + 127) / 128;    // 782 GEMM row-blocks
    const int half1 = (nblk + 1) / 2;     // 391
    const int half2 = nblk - half1;       // 391
    const int eblk  = (E + T - 1) / T;    // 12500 edge blocks

    k_reset<<<(n + T - 1) / T, T>>>(n);
    // GEMM1 (first half) overlapped with degree histogram
    k_deg_gemm1<<<half1 + eblk, T>>>(col, ew, E, x, W1, n, half1);
    k_scan1<<<nb, SCAN_B>>>(n);
    k_scan2<<<1, 128>>>(nb);
    k_scan3<<<(n + T - 1) / T, T>>>(batch, n, E);
    // GEMM1 (second half) overlapped with edge placement
    k_place_gemm1<<<half2 + eblk, T>>>(row, col, ew, E, x, W1, n, half2, half1);

    k_gather<<<(n * 8 + T - 1) / T, T>>>(b1, n);              // layer 1

    k_gemm2<<<nblk, T>>>(W2, n);                              // layer 2
    k_gather<<<(n * 8 + T - 1) / T, T>>>(b2, n);

    k_pool <<<G_NUM, 256>>>(n);
    k_final<<<1, T>>>(Wc, bc, out);
}